// round 14
// baseline (speedup 1.0000x reference)
#include <cuda_runtime.h>

// Problem constants
#define TT     2048
#define CELLS  2048
#define NSEG   128
#define SEGLEN (TT / NSEG)    // 16
#define CHUNK  16             // == SEGLEN: one boundary per chunk
#define NCHUNK (TT / CHUNK)   // 128

// Scratch: boundary states entering each segment (seg 1..NSEG-1).
__device__ float2 g_bound[NSEG * CELLS];

// ---------------------------------------------------------------------------
// Pass 1: serial boundary scan. 1 thread/cell, 64 blocks x 32 threads
// (one warp per SM, exclusive SMSP). 6-stage rotating register prefetch:
// chunk consumed 5 chunks (80 iters ~ 1200 cyc of compute) after its load
// issues -> covers full DRAM latency (~1050 cyc @NAT); no warm kernel needed.
// One LDG interleaved per step.
// S1 chain: S1' = max( fma(S1, c1 - E/smax, P), max(fma(S1, c1, P - E), 0) )
// S2 as U = S2/k2: U' = fma(U, c2, S1_old); clamp provably inactive in-scan.
// ---------------------------------------------------------------------------
__global__ __launch_bounds__(32, 1)
void pass1_kernel(const float2* __restrict__ F2,   // forcings [T, CELLS]
                  const float2* __restrict__ S02,  // initial states [CELLS]
                  const float4* __restrict__ P4)   // params [CELLS]
{
    const int cell = blockIdx.x * 32 + threadIdx.x;

    const float4 u = P4[cell];
    const float smax = 10.0f  + 490.0f  * u.x;
    const float k1   = 0.01f  + 0.89f   * u.y;
    const float k2   = 0.001f + 0.199f  * u.z;
    const float kb   = 0.001f + 0.099f  * u.w;

    const float inv  = 1.0f / smax;
    const float ninv = -inv;
    const float c1   = 1.0f - k1 - k2;
    const float c2   = 1.0f - kb;

    float2 s = S02[cell];
    float S1 = s.x;
    float U  = s.y / k2;          // S2 = k2 * U

    const float2* __restrict__ F = F2 + cell;

#define LOADC(buf, ci)                                           \
    do {                                                         \
        const float2* Fp = F + (size_t)(ci) * CHUNK * CELLS;     \
        _Pragma("unroll")                                        \
        for (int i = 0; i < CHUNK; i++)                          \
            (buf)[i] = Fp[i * CELLS];                            \
    } while (0)

    // Process chunk pci while issuing loads for chunk lci (1 LDG per step);
    // lci clamped at the tail (redundant reload, never consumed).
#define PROC_LOAD(pbuf, pci, lbuf, lci_raw)                      \
    do {                                                         \
        const int lci = ((lci_raw) < NCHUNK) ? (lci_raw)         \
                                             : (NCHUNK - 1);     \
        const float2* Fp = F + (size_t)lci * CHUNK * CELLS;      \
        _Pragma("unroll")                                        \
        for (int i = 0; i < CHUNK; i++) {                        \
            (lbuf)[i] = Fp[i * CELLS];                           \
            const float Pf  = (pbuf)[i].x;                       \
            const float Ef  = (pbuf)[i].y;                       \
            const float caa = fmaf(ninv, Ef, c1);                \
            const float pme = Pf - Ef;                           \
            const float t1  = fmaf(S1, caa, Pf);                 \
            const float t2  = fmaf(S1, c1, pme);                 \
            U = fmaf(U, c2, S1);          /* old S1 */           \
            const float m = fmaxf(t2, 0.0f);                     \
            S1 = fmaxf(t1, m);                                   \
        }                                                        \
        if ((pci) != NCHUNK - 1)                                 \
            g_bound[((pci) + 1) * CELLS + cell] =                \
                make_float2(S1, k2 * U);                         \
    } while (0)

    float2 bufA[CHUNK], bufB[CHUNK], bufC[CHUNK],
           bufD[CHUNK], bufE[CHUNK], bufF[CHUNK];

    LOADC(bufA, 0);
    LOADC(bufB, 1);
    LOADC(bufC, 2);
    LOADC(bufD, 3);
    LOADC(bufE, 4);

    // 21 groups of 6 chunks = 126; epilogue handles chunks 126, 127.
#pragma unroll 1
    for (int c = 0; c < 126; c += 6) {
        PROC_LOAD(bufA, c,     bufF, c + 5);
        PROC_LOAD(bufB, c + 1, bufA, c + 6);
        PROC_LOAD(bufC, c + 2, bufB, c + 7);
        PROC_LOAD(bufD, c + 3, bufC, c + 8);
        PROC_LOAD(bufE, c + 4, bufD, c + 9);
        PROC_LOAD(bufF, c + 5, bufE, c + 10);
    }
    // After the loop: chunk 126 is in bufA, chunk 127 in bufB.
    PROC_LOAD(bufA, 126, bufC, 127);   // redundant load, harmless
    PROC_LOAD(bufB, 127, bufD, 127);   // redundant load, harmless
#undef LOADC
#undef PROC_LOAD
}

// ---------------------------------------------------------------------------
// Pass 2: parallel segment replay. One thread = (cell, segment).
// Replays SEGLEN steps from the boundary state, writing fluxes AND states
// with reference-faithful arithmetic. At its memory roofline (~21us).
// ---------------------------------------------------------------------------
__global__ __launch_bounds__(256)
void pass2_kernel(const float2* __restrict__ F2,   // forcings [T, CELLS]
                  const float2* __restrict__ S02,  // initial states [CELLS]
                  const float4* __restrict__ P4,   // params [CELLS]
                  float4* __restrict__ FX4,        // fluxes [T, CELLS]
                  float2* __restrict__ ST2)        // states [T, CELLS]
{
    const int cell = blockIdx.x * 256 + threadIdx.x;
    const int seg  = blockIdx.y;
    const int t0   = seg * SEGLEN;

    const float4 u = P4[cell];
    const float smax = 10.0f  + 490.0f  * u.x;
    const float k1   = 0.01f  + 0.89f   * u.y;
    const float k2   = 0.001f + 0.199f  * u.z;
    const float kb   = 0.001f + 0.099f  * u.w;
    const float inv  = 1.0f / smax;

    float2 s = (seg == 0) ? S02[cell] : g_bound[seg * CELLS + cell];
    float S1 = s.x, S2 = s.y;

    const float2* __restrict__ F  = F2  + (size_t)t0 * CELLS + cell;
    float4*       __restrict__ FX = FX4 + (size_t)t0 * CELLS + cell;
    float2*       __restrict__ ST = ST2 + (size_t)t0 * CELLS + cell;

#pragma unroll 8
    for (int i = 0; i < SEGLEN; i++) {
        const float2 f  = F[i * CELLS];
        const float P   = f.x;
        const float PET = f.y;

        const float frac = fminf(S1 * inv, 1.0f);   // S1 >= 0 always
        const float et   = PET * frac;
        const float q1   = k1 * S1;
        const float perc = k2 * S1;
        const float qb   = kb * S2;

        FX[i * CELLS] = make_float4(et, q1, perc, qb);

        S1 = fmaxf(S1 + P - et - q1 - perc, 0.0f);
        S2 = fmaxf(S2 + perc - qb, 0.0f);

        ST[i * CELLS] = make_float2(S1, S2);
    }
}

extern "C" void kernel_launch(void* const* d_in, const int* in_sizes, int n_in,
                              void* d_out, int out_size)
{
    const float* forcings = (const float*)d_in[0];   // [T,B,H,2]
    const float* states0  = (const float*)d_in[1];   // [B,H,2]
    const float* params   = (const float*)d_in[2];   // [B,H,4]

    float* out = (float*)d_out;
    float* fluxes_out = out;                                   // [T,B,H,4]
    float* states_out = out + (size_t)TT * CELLS * 4;          // [T,B,H,2]

    pass1_kernel<<<CELLS / 32, 32>>>(
        reinterpret_cast<const float2*>(forcings),
        reinterpret_cast<const float2*>(states0),
        reinterpret_cast<const float4*>(params));

    pass2_kernel<<<dim3(CELLS / 256, NSEG), 256>>>(
        reinterpret_cast<const float2*>(forcings),
        reinterpret_cast<const float2*>(states0),
        reinterpret_cast<const float4*>(params),
        reinterpret_cast<float4*>(fluxes_out),
        reinterpret_cast<float2*>(states_out));
}